// round 4
// baseline (speedup 1.0000x reference)
#include <cuda_runtime.h>
#include <cuda_bf16.h>

namespace {

constexpr int Bc = 2, Hc = 16, Sc = 2048, Dc = 64;
constexpr int BM = 16;     // query rows per block
constexpr int BN = 128;    // key tile
constexpr int NT = 256;    // threads per block
constexpr float NEGV = -1e9f;
constexpr int DP = Dc + 4; // padded smem row

struct Smem {
    float scores[BM][Sc];   // 128 KB, reused as probabilities
    float q[BM][DP];        // 4.25 KB
    float k[BN][DP];        // 34 KB
};

__global__ void __launch_bounds__(NT, 1)
attn_kernel(const float* __restrict__ gq,
            const float* __restrict__ gk,
            const float* __restrict__ gv,
            const int*   __restrict__ gmask,
            float* __restrict__ gout,    // [B,H,S,D] or null
            float* __restrict__ gattn)   // [B,H,S,S] or null
{
    extern __shared__ char smem_raw[];
    Smem& sm = *reinterpret_cast<Smem*>(smem_raw);

    const int bh  = blockIdx.y;           // 0..B*H-1
    const int q0  = blockIdx.x * BM;      // query tile start
    const int tid = threadIdx.x;
    const size_t base = (size_t)bh * Sc * Dc;   // q/k/v/out all [BH, S, D]

    // ---- load Q tile -------------------------------------------------------
    for (int i = tid; i < BM * Dc; i += NT) {
        int r = i / Dc, c = i % Dc;
        sm.q[r][c] = gq[base + (size_t)(q0 + r) * Dc + c];
    }

    const int qi = tid & 15;     // query row handled by this thread
    const int kg = tid >> 4;     // key group (8 keys) / d group (4 dims)
    const float inv_temp = 0.125f;  // 1/sqrt(64)

    // ---- S = Q K^T / temp, masked, into smem scores ------------------------
    for (int kt = 0; kt < Sc / BN; ++kt) {
        __syncthreads();   // previous tile's compute done before K reload
        for (int i = tid; i < BN * Dc; i += NT) {
            int r = i / Dc, c = i % Dc;
            sm.k[r][c] = gk[base + (size_t)(kt * BN + r) * Dc + c];
        }
        __syncthreads();

        float acc[8];
        #pragma unroll
        for (int u = 0; u < 8; ++u) acc[u] = 0.f;

        #pragma unroll
        for (int d0 = 0; d0 < Dc; d0 += 4) {
            float4 qv = *reinterpret_cast<const float4*>(&sm.q[qi][d0]);
            #pragma unroll
            for (int u = 0; u < 8; ++u) {
                float4 kv = *reinterpret_cast<const float4*>(&sm.k[kg * 8 + u][d0]);
                acc[u] = fmaf(qv.x, kv.x, acc[u]);
                acc[u] = fmaf(qv.y, kv.y, acc[u]);
                acc[u] = fmaf(qv.z, kv.z, acc[u]);
                acc[u] = fmaf(qv.w, kv.w, acc[u]);
            }
        }

        const int jbase = kt * BN + kg * 8;
        const size_t mrow = (size_t)(q0 + qi) * Sc;
        #pragma unroll
        for (int u = 0; u < 8; ++u) {
            int j = jbase + u;
            int m = gmask[mrow + j];
            sm.scores[qi][j] = (m == 0) ? NEGV : acc[u] * inv_temp;
        }
    }
    __syncthreads();

    // ---- row softmax (warp w owns rows 2w, 2w+1) ---------------------------
    {
        const int lane = tid & 31, w = tid >> 5;
        #pragma unroll
        for (int rr = 0; rr < 2; ++rr) {
            const int r = w * 2 + rr;
            float m = -3.4e38f;
            for (int i = lane; i < Sc; i += 32)
                m = fmaxf(m, sm.scores[r][i]);
            #pragma unroll
            for (int o = 16; o; o >>= 1)
                m = fmaxf(m, __shfl_xor_sync(0xffffffffu, m, o));

            float l = 0.f;
            for (int i = lane; i < Sc; i += 32) {
                float p = __expf(sm.scores[r][i] - m);
                sm.scores[r][i] = p;
                l += p;
            }
            #pragma unroll
            for (int o = 16; o; o >>= 1)
                l += __shfl_xor_sync(0xffffffffu, l, o);
            const float inv = 1.f / l;

            float4* arow = gattn
                ? reinterpret_cast<float4*>(gattn + ((size_t)bh * Sc + (q0 + r)) * Sc)
                : nullptr;
            float4* srow = reinterpret_cast<float4*>(sm.scores[r]);
            for (int i = lane; i < Sc / 4; i += 32) {
                float4 p4 = srow[i];
                p4.x *= inv; p4.y *= inv; p4.z *= inv; p4.w *= inv;
                srow[i] = p4;
                if (arow) arow[i] = p4;
            }
        }
    }
    __syncthreads();

    // ---- O = P V  (thread: row qi, dims kg*4..kg*4+3) ----------------------
    if (gout) {
        float4 o = make_float4(0.f, 0.f, 0.f, 0.f);
        const float* vb = gv + base + (size_t)kg * 4;
        const float* prow = sm.scores[qi];
        for (int k0 = 0; k0 < Sc; k0 += 4) {
            float4 p4 = *reinterpret_cast<const float4*>(&prow[k0]);
            float4 v0 = *reinterpret_cast<const float4*>(&vb[(size_t)(k0 + 0) * Dc]);
            float4 v1 = *reinterpret_cast<const float4*>(&vb[(size_t)(k0 + 1) * Dc]);
            float4 v2 = *reinterpret_cast<const float4*>(&vb[(size_t)(k0 + 2) * Dc]);
            float4 v3 = *reinterpret_cast<const float4*>(&vb[(size_t)(k0 + 3) * Dc]);
            o.x = fmaf(p4.x, v0.x, o.x); o.y = fmaf(p4.x, v0.y, o.y);
            o.z = fmaf(p4.x, v0.z, o.z); o.w = fmaf(p4.x, v0.w, o.w);
            o.x = fmaf(p4.y, v1.x, o.x); o.y = fmaf(p4.y, v1.y, o.y);
            o.z = fmaf(p4.y, v1.z, o.z); o.w = fmaf(p4.y, v1.w, o.w);
            o.x = fmaf(p4.z, v2.x, o.x); o.y = fmaf(p4.z, v2.y, o.y);
            o.z = fmaf(p4.z, v2.z, o.z); o.w = fmaf(p4.z, v2.w, o.w);
            o.x = fmaf(p4.w, v3.x, o.x); o.y = fmaf(p4.w, v3.y, o.y);
            o.z = fmaf(p4.w, v3.z, o.z); o.w = fmaf(p4.w, v3.w, o.w);
        }
        *reinterpret_cast<float4*>(
            gout + base + (size_t)(q0 + qi) * Dc + kg * 4) = o;
    }
}

} // namespace

extern "C" void kernel_launch(void* const* d_in, const int* in_sizes, int n_in,
                              void* d_out, int out_size)
{
    const float* q    = (const float*)d_in[0];
    const float* k    = (const float*)d_in[1];
    const float* v    = (const float*)d_in[2];
    const int*   mask = (const int*)d_in[3];

    const size_t nOut  = (size_t)Bc * Hc * Sc * Dc;   // 4,194,304
    const size_t nAttn = (size_t)Bc * Hc * Sc * Sc;   // 134,217,728

    float* outp  = nullptr;
    float* attnp = nullptr;
    float* base  = (float*)d_out;
    if ((size_t)out_size >= nOut + nAttn) {           // tuple (output, attn)
        outp  = base;
        attnp = base + nOut;
    } else if ((size_t)out_size == nAttn) {           // attn only
        attnp = base;
    } else {                                          // output only
        outp = base;
    }

    cudaFuncSetAttribute(attn_kernel,
                         cudaFuncAttributeMaxDynamicSharedMemorySize,
                         (int)sizeof(Smem));

    dim3 grid(Sc / BM, Bc * Hc);   // (128, 32)
    attn_kernel<<<grid, NT, sizeof(Smem)>>>(q, k, v, mask, outp, attnp);
}

// round 6
// speedup vs baseline: 11.5247x; 11.5247x over previous
#include <cuda_runtime.h>
#include <cuda_bf16.h>
#include <cstdint>

namespace {

constexpr int Bc = 2, Hc = 16, Sc = 2048, Dc = 64;
constexpr int BM = 128, BN = 128, NT = 256, NKT = Sc / BN;
constexpr float NEGV = -1e9f, INVT = 0.125f;
constexpr int RS = 72;                       // smem row stride in bf16 (144B, conflict-free)

constexpr int QHI = 0, QLO = BM * RS, KHI = 2 * BM * RS, KLO = 3 * BM * RS;
constexpr int SMEM_BYTES = 4 * BM * RS * 2;  // 73728

__device__ __forceinline__ uint32_t smem_u32(const void* p) {
    uint32_t a;
    asm("{ .reg .u64 t; cvta.to.shared.u64 t, %1; cvt.u32.u64 %0, t; }" : "=r"(a) : "l"(p));
    return a;
}
__device__ __forceinline__ void ldm4(uint32_t& r0, uint32_t& r1, uint32_t& r2, uint32_t& r3, uint32_t a) {
    asm volatile("ldmatrix.sync.aligned.m8n8.x4.shared.b16 {%0,%1,%2,%3}, [%4];"
                 : "=r"(r0), "=r"(r1), "=r"(r2), "=r"(r3) : "r"(a));
}
__device__ __forceinline__ void ldm4t(uint32_t& r0, uint32_t& r1, uint32_t& r2, uint32_t& r3, uint32_t a) {
    asm volatile("ldmatrix.sync.aligned.m8n8.x4.trans.shared.b16 {%0,%1,%2,%3}, [%4];"
                 : "=r"(r0), "=r"(r1), "=r"(r2), "=r"(r3) : "r"(a));
}
__device__ __forceinline__ void mma_bf16(float* c, const uint32_t* a, uint32_t b0, uint32_t b1) {
    asm volatile("mma.sync.aligned.m16n8k16.row.col.f32.bf16.bf16.f32 "
                 "{%0,%1,%2,%3}, {%4,%5,%6,%7}, {%8,%9}, {%0,%1,%2,%3};"
                 : "+f"(c[0]), "+f"(c[1]), "+f"(c[2]), "+f"(c[3])
                 : "r"(a[0]), "r"(a[1]), "r"(a[2]), "r"(a[3]), "r"(b0), "r"(b1));
}
__device__ __forceinline__ void split2(float x, float y, uint32_t& hi, uint32_t& lo) {
    __nv_bfloat162 h = __floats2bfloat162_rn(x, y);
    __nv_bfloat162 l = __floats2bfloat162_rn(x - __bfloat162float(h.x),
                                             y - __bfloat162float(h.y));
    hi = *reinterpret_cast<uint32_t*>(&h);
    lo = *reinterpret_cast<uint32_t*>(&l);
}

// stage a [128 x 64] f32 tile into split hi/lo bf16 smem tiles (144B rows)
__device__ __forceinline__ void stage_tile(const float* __restrict__ g,
                                           __nv_bfloat16* hi, __nv_bfloat16* lo, int tid) {
    const float4* g4 = reinterpret_cast<const float4*>(g);
    for (int i = tid; i < BM * 16; i += NT) {
        const int r = i >> 4, c4 = (i & 15) << 2;
        float4 f = g4[i];
        uint32_t h0, l0, h1, l1;
        split2(f.x, f.y, h0, l0);
        split2(f.z, f.w, h1, l1);
        *reinterpret_cast<uint2*>(hi + r * RS + c4) = make_uint2(h0, h1);
        *reinterpret_cast<uint2*>(lo + r * RS + c4) = make_uint2(l0, l1);
    }
}

__global__ void __launch_bounds__(NT, 2)
attn_mma(const float* __restrict__ gq, const float* __restrict__ gk,
         const float* __restrict__ gv, const int* __restrict__ gmask,
         float* __restrict__ gout, float* __restrict__ gattn)
{
    extern __shared__ __nv_bfloat16 sm[];
    const int tid = threadIdx.x, lane = tid & 31, w = tid >> 5;
    const int bh = blockIdx.y, q0 = blockIdx.x * BM;
    const size_t gbase = (size_t)bh * Sc * Dc;

    __nv_bfloat16 *qhi = sm + QHI, *qlo = sm + QLO, *khi = sm + KHI, *klo = sm + KLO;
    const uint32_t qhiA = smem_u32(qhi), qloA = smem_u32(qlo);
    const uint32_t khiA = smem_u32(khi), kloA = smem_u32(klo);

    // ldmatrix lane addressing (same formula for all x4 loads)
    const int lrow = (lane & 7) + ((lane >> 3) & 1) * 8;
    const int lcol = (lane >> 4) * 8;

    const int r0 = w * 16 + (lane >> 2);           // this thread's rows: r0, r0+8
    const int jq = (lane & 3) * 2;                 // col offset within 8-col fragment
    float* arow0 = gattn + ((size_t)bh * Sc + q0 + r0) * Sc;
    float* arow1 = arow0 + (size_t)8 * Sc;
    const int* mrow0 = gmask + (size_t)(q0 + r0) * Sc;
    const int* mrow1 = mrow0 + 8 * Sc;

    stage_tile(gq + gbase + (size_t)q0 * Dc, qhi, qlo, tid);

    float mA = -3.4e38f, lA = 0.f, mB = -3.4e38f, lB = 0.f;

    // ================= PASS 1: S = QK^T, raw scores out, online (m,l) =======
    for (int kt = 0; kt < NKT; ++kt) {
        __syncthreads();
        stage_tile(gk + gbase + (size_t)(kt * BN) * Dc, khi, klo, tid);
        __syncthreads();

        float sacc[16][4];
        #pragma unroll
        for (int nf = 0; nf < 16; ++nf)
            sacc[nf][0] = sacc[nf][1] = sacc[nf][2] = sacc[nf][3] = 0.f;

        #pragma unroll
        for (int ks = 0; ks < 4; ++ks) {
            uint32_t ah[4], al[4];
            const uint32_t qoff = (uint32_t)(((w * 16 + lrow) * RS + ks * 16 + lcol) * 2);
            ldm4(ah[0], ah[1], ah[2], ah[3], qhiA + qoff);
            ldm4(al[0], al[1], al[2], al[3], qloA + qoff);
            #pragma unroll
            for (int nf2 = 0; nf2 < 8; ++nf2) {
                uint32_t bh_[4], bl_[4];
                const uint32_t koff = (uint32_t)(((nf2 * 16 + lrow) * RS + ks * 16 + lcol) * 2);
                ldm4(bh_[0], bh_[1], bh_[2], bh_[3], khiA + koff);
                ldm4(bl_[0], bl_[1], bl_[2], bl_[3], kloA + koff);
                mma_bf16(sacc[2 * nf2],     ah, bh_[0], bh_[2]);
                mma_bf16(sacc[2 * nf2],     ah, bl_[0], bl_[2]);
                mma_bf16(sacc[2 * nf2],     al, bh_[0], bh_[2]);
                mma_bf16(sacc[2 * nf2 + 1], ah, bh_[1], bh_[3]);
                mma_bf16(sacc[2 * nf2 + 1], ah, bl_[1], bl_[3]);
                mma_bf16(sacc[2 * nf2 + 1], al, bh_[1], bh_[3]);
            }
        }

        float tmax0 = -3.4e38f, tmax1 = -3.4e38f;
        #pragma unroll
        for (int nf = 0; nf < 16; ++nf) {
            const int jc = kt * BN + nf * 8 + jq;
            int2 m0 = *reinterpret_cast<const int2*>(mrow0 + jc);
            int2 m1 = *reinterpret_cast<const int2*>(mrow1 + jc);
            float s0 = m0.x ? sacc[nf][0] * INVT : NEGV;
            float s1 = m0.y ? sacc[nf][1] * INVT : NEGV;
            float s2 = m1.x ? sacc[nf][2] * INVT : NEGV;
            float s3 = m1.y ? sacc[nf][3] * INVT : NEGV;
            sacc[nf][0] = s0; sacc[nf][1] = s1; sacc[nf][2] = s2; sacc[nf][3] = s3;
            *reinterpret_cast<float2*>(arow0 + jc) = make_float2(s0, s1);
            *reinterpret_cast<float2*>(arow1 + jc) = make_float2(s2, s3);
            tmax0 = fmaxf(tmax0, fmaxf(s0, s1));
            tmax1 = fmaxf(tmax1, fmaxf(s2, s3));
        }
        if (tmax0 > mA) { lA *= __expf(mA - tmax0); mA = tmax0; }
        if (tmax1 > mB) { lB *= __expf(mB - tmax1); mB = tmax1; }
        float a0 = 0.f, a1 = 0.f;
        #pragma unroll
        for (int nf = 0; nf < 16; ++nf) {
            a0 += __expf(sacc[nf][0] - mA) + __expf(sacc[nf][1] - mA);
            a1 += __expf(sacc[nf][2] - mB) + __expf(sacc[nf][3] - mB);
        }
        lA += a0; lB += a1;
    }

    // quad reduction (lanes sharing a row: lane%4 varies)
    #pragma unroll
    for (int off = 1; off < 4; off <<= 1) {
        float mo = __shfl_xor_sync(0xffffffffu, mA, off);
        float lo = __shfl_xor_sync(0xffffffffu, lA, off);
        float mn = fmaxf(mA, mo);
        lA = lA * __expf(mA - mn) + lo * __expf(mo - mn); mA = mn;
        mo = __shfl_xor_sync(0xffffffffu, mB, off);
        lo = __shfl_xor_sync(0xffffffffu, lB, off);
        mn = fmaxf(mB, mo);
        lB = lB * __expf(mB - mn) + lo * __expf(mo - mn); mB = mn;
    }
    const float liA = 1.f / lA, liB = 1.f / lB;

    // ================= PASS 2: finalize attn + O = P V ======================
    float oacc[8][4];
    #pragma unroll
    for (int nv = 0; nv < 8; ++nv)
        oacc[nv][0] = oacc[nv][1] = oacc[nv][2] = oacc[nv][3] = 0.f;

    for (int kt = 0; kt < NKT; ++kt) {
        __syncthreads();
        stage_tile(gv + gbase + (size_t)(kt * BN) * Dc, khi, klo, tid);   // V reuses K buffers
        __syncthreads();

        #pragma unroll
        for (int ks = 0; ks < 8; ++ks) {
            uint32_t ah[4], al[4];
            #pragma unroll
            for (int u = 0; u < 2; ++u) {
                const int jc = kt * BN + (2 * ks + u) * 8 + jq;
                float2 sa = *reinterpret_cast<const float2*>(arow0 + jc);
                float2 sb = *reinterpret_cast<const float2*>(arow1 + jc);
                float p0 = __expf(sa.x - mA) * liA, p1 = __expf(sa.y - mA) * liA;
                float p2 = __expf(sb.x - mB) * liB, p3 = __expf(sb.y - mB) * liB;
                *reinterpret_cast<float2*>(arow0 + jc) = make_float2(p0, p1);
                *reinterpret_cast<float2*>(arow1 + jc) = make_float2(p2, p3);
                split2(p0, p1, ah[2 * u], al[2 * u]);            // C-frag == A-frag layout
                split2(p2, p3, ah[2 * u + 1], al[2 * u + 1]);
            }
            #pragma unroll
            for (int nv2 = 0; nv2 < 4; ++nv2) {
                uint32_t bh_[4], bl_[4];
                const uint32_t voff = (uint32_t)(((ks * 16 + lrow) * RS + nv2 * 16 + lcol) * 2);
                ldm4t(bh_[0], bh_[1], bh_[2], bh_[3], khiA + voff);
                ldm4t(bl_[0], bl_[1], bl_[2], bl_[3], kloA + voff);
                mma_bf16(oacc[2 * nv2],     ah, bh_[0], bh_[1]);
                mma_bf16(oacc[2 * nv2],     ah, bl_[0], bl_[1]);
                mma_bf16(oacc[2 * nv2],     al, bh_[0], bh_[1]);
                mma_bf16(oacc[2 * nv2 + 1], ah, bh_[2], bh_[3]);
                mma_bf16(oacc[2 * nv2 + 1], ah, bl_[2], bl_[3]);
                mma_bf16(oacc[2 * nv2 + 1], al, bh_[2], bh_[3]);
            }
        }
    }

    if (gout) {
        float* orow0 = gout + gbase + (size_t)(q0 + r0) * Dc;
        float* orow1 = orow0 + 8 * Dc;
        #pragma unroll
        for (int nv = 0; nv < 8; ++nv) {
            const int dc = nv * 8 + jq;
            *reinterpret_cast<float2*>(orow0 + dc) = make_float2(oacc[nv][0], oacc[nv][1]);
            *reinterpret_cast<float2*>(orow1 + dc) = make_float2(oacc[nv][2], oacc[nv][3]);
        }
    }
}

} // namespace

extern "C" void kernel_launch(void* const* d_in, const int* in_sizes, int n_in,
                              void* d_out, int out_size)
{
    const float* q    = (const float*)d_in[0];
    const float* k    = (const float*)d_in[1];
    const float* v    = (const float*)d_in[2];
    const int*   mask = (const int*)d_in[3];

    const size_t nOut  = (size_t)Bc * Hc * Sc * Dc;
    const size_t nAttn = (size_t)Bc * Hc * Sc * Sc;

    float* base  = (float*)d_out;
    float* outp  = nullptr;
    float* attnp = nullptr;
    if ((size_t)out_size >= nOut + nAttn) { outp = base; attnp = base + nOut; }
    else if ((size_t)out_size == nAttn)   { attnp = base; }
    else                                  { outp = base; attnp = base; }

    cudaFuncSetAttribute(attn_mma, cudaFuncAttributeMaxDynamicSharedMemorySize, SMEM_BYTES);
    dim3 grid(Sc / BM, Bc * Hc);   // (16, 32)
    attn_mma<<<grid, NT, SMEM_BYTES>>>(q, k, v, mask, outp, attnp);
}